// round 2
// baseline (speedup 1.0000x reference)
#include <cuda_runtime.h>
#include <math.h>

#define TOK 32768

// -------------------- scratch (device globals; no allocs) --------------------
__device__ float g_xt  [(size_t)TOK*128];
__device__ float g_xz  [(size_t)TOK*512];
__device__ float g_u   [(size_t)TOK*256];
__device__ float g_xdbl[(size_t)TOK*40];
__device__ float g_dtb [(size_t)TOK*256];
__device__ float g_gy  [(size_t)TOK*256];
__device__ float g_mean[4*32*128];
__device__ float g_Pd  [4*32];

__device__ __forceinline__ float siluf(float v){ return v / (1.f + __expf(-v)); }

// -------------------- gather x -> x_t (B*C, L, D) --------------------
// x_t[(b*32+c)*256 + l][d] = x[((b*256+l)*32+c)*128 + d]
__global__ void gather_xt_kernel(const float* __restrict__ x, float* __restrict__ xt){
  int idx = blockIdx.x*blockDim.x + threadIdx.x;
  int d = idx & 127;
  int t = idx >> 7;
  int l = t & 255;
  int n = t >> 8;
  int c = n & 31;
  int b = n >> 5;
  xt[idx] = x[(((size_t)(b*256+l)*32+c)*128) + d];
}

// -------------------- generic fp32 tiled GEMM: C = A(MxK) @ W(KxN) --------------------
// mode 0: row-major write; mode 1: T-scatter (N must be 128):
//   row r = n*256+l with n=b*32+c  ->  out[((b*256+l)*32+c)*128 + col]
__global__ void gemm_kernel(const float* __restrict__ A, const float* __restrict__ W,
                            float* __restrict__ Cout, int M, int N, int K, int mode)
{
  const int BM=64, BN=64, BK=16;
  __shared__ float As[BK][BM];
  __shared__ float Ws[BK][BN];
  int tid = threadIdx.x;           // 256 threads
  int tr = tid >> 4;               // 0..15
  int tc = tid & 15;               // 0..15
  int row0 = blockIdx.y * BM;
  int col0 = blockIdx.x * BN;

  float acc[4][4];
  #pragma unroll
  for (int i=0;i<4;i++)
    #pragma unroll
    for (int j=0;j<4;j++) acc[i][j]=0.f;

  int ar = tid >> 2;               // 0..63
  int ak = (tid & 3) * 4;          // 0,4,8,12
  int wr = tid >> 4;               // 0..15
  int wc = (tid & 15) * 4;         // 0..60

  for (int k0=0; k0<K; k0+=BK){
    // A tile (rows always valid: M % 64 == 0; K % 16 == 0)
    float4 av = *reinterpret_cast<const float4*>(A + (size_t)(row0+ar)*K + k0 + ak);
    As[ak+0][ar]=av.x; As[ak+1][ar]=av.y; As[ak+2][ar]=av.z; As[ak+3][ar]=av.w;
    // W tile (guard N=40 case)
    int wcol = col0 + wc;
    if (wcol + 3 < N) {
      float4 wv = *reinterpret_cast<const float4*>(W + (size_t)(k0+wr)*N + wcol);
      *reinterpret_cast<float4*>(&Ws[wr][wc]) = wv;
    } else {
      #pragma unroll
      for (int j=0;j<4;j++)
        Ws[wr][wc+j] = (wcol+j < N) ? W[(size_t)(k0+wr)*N + wcol + j] : 0.f;
    }
    __syncthreads();
    #pragma unroll
    for (int k=0;k<BK;k++){
      float4 a = *reinterpret_cast<const float4*>(&As[k][tr*4]);
      float4 w = *reinterpret_cast<const float4*>(&Ws[k][tc*4]);
      acc[0][0]=fmaf(a.x,w.x,acc[0][0]); acc[0][1]=fmaf(a.x,w.y,acc[0][1]);
      acc[0][2]=fmaf(a.x,w.z,acc[0][2]); acc[0][3]=fmaf(a.x,w.w,acc[0][3]);
      acc[1][0]=fmaf(a.y,w.x,acc[1][0]); acc[1][1]=fmaf(a.y,w.y,acc[1][1]);
      acc[1][2]=fmaf(a.y,w.z,acc[1][2]); acc[1][3]=fmaf(a.y,w.w,acc[1][3]);
      acc[2][0]=fmaf(a.z,w.x,acc[2][0]); acc[2][1]=fmaf(a.z,w.y,acc[2][1]);
      acc[2][2]=fmaf(a.z,w.z,acc[2][2]); acc[2][3]=fmaf(a.z,w.w,acc[2][3]);
      acc[3][0]=fmaf(a.w,w.x,acc[3][0]); acc[3][1]=fmaf(a.w,w.y,acc[3][1]);
      acc[3][2]=fmaf(a.w,w.z,acc[3][2]); acc[3][3]=fmaf(a.w,w.w,acc[3][3]);
    }
    __syncthreads();
  }

  int row = row0 + tr*4;
  int col = col0 + tc*4;
  if (mode == 0) {
    #pragma unroll
    for (int i=0;i<4;i++){
      int r = row+i;
      #pragma unroll
      for (int j=0;j<4;j++)
        if (col+j < N) Cout[(size_t)r*N + col + j] = acc[i][j];
    }
  } else {
    #pragma unroll
    for (int i=0;i<4;i++){
      int r = row+i;
      int l = r & 255; int n = r >> 8; int c = n & 31; int b = n >> 5;
      size_t orow = ((size_t)(b*256+l)*32 + c) * 128;
      #pragma unroll
      for (int j=0;j<4;j++)
        Cout[orow + col + j] = acc[i][j];
    }
  }
}

// -------------------- causal depthwise conv (DC=4) + bias + silu --------------------
// reads u-half of xz (cols 0..255), writes u (N*Lseq, 256)
__global__ void conv_silu_kernel(const float* __restrict__ xz, const float* __restrict__ cw,
                                 const float* __restrict__ cb, float* __restrict__ uo, int Lseq){
  int n = blockIdx.x; int d = threadIdx.x;
  float w0=cw[d], w1=cw[256+d], w2=cw[512+d], w3=cw[768+d];
  float b = cb[d];
  const float* base = xz + (size_t)n*Lseq*512;
  float* ub = uo + (size_t)n*Lseq*256;
  float x0=0.f, x1=0.f, x2=0.f;
  for (int l=0;l<Lseq;l++){
    float x3 = base[(size_t)l*512 + d];
    float v = fmaf(x0,w0, fmaf(x1,w1, fmaf(x2,w2, fmaf(x3,w3, b))));
    ub[(size_t)l*256 + d] = siluf(v);
    x0=x1; x1=x2; x2=x3;
  }
}

// -------------------- dt = softplus(xdbl[:, :8] @ w_dt + b_dt) --------------------
__global__ void dt_kernel(const float* __restrict__ xdbl, const float* __restrict__ w_dt,
                          const float* __restrict__ b_dt, float* __restrict__ dt){
  int d = threadIdx.x;                        // 256
  size_t t0 = (size_t)blockIdx.x * 16;
  float w[8];
  #pragma unroll
  for (int r=0;r<8;r++) w[r] = w_dt[r*256 + d];
  float b = b_dt[d];
  __shared__ float xs[16][8];
  if (d < 128) xs[d>>3][d&7] = xdbl[(t0 + (d>>3))*40 + (d&7)];
  __syncthreads();
  for (int i=0;i<16;i++){
    float acc = b;
    #pragma unroll
    for (int r=0;r<8;r++) acc = fmaf(xs[i][r], w[r], acc);
    float sp = (acc > 20.f) ? acc : log1pf(__expf(acc));
    dt[(t0+i)*256 + d] = sp;
  }
}

// -------------------- selective scan fused with output gating --------------------
// gy[t,d] = (sum_s h[d,s]*C[s] + u*Dskip[d]) * silu(z[t,d])
__global__ void scan_gate_kernel(const float* __restrict__ dt, const float* __restrict__ u,
                                 const float* __restrict__ xdbl, const float* __restrict__ a_log,
                                 const float* __restrict__ dskip, const float* __restrict__ xz,
                                 float* __restrict__ gy, int Lseq)
{
  int n = blockIdx.x; int d = threadIdx.x;    // 256
  float A[16];
  #pragma unroll
  for (int s=0;s<16;s++) A[s] = -__expf(a_log[d*16+s]);
  float Dd = dskip[d];
  float h[16];
  #pragma unroll
  for (int s=0;s<16;s++) h[s]=0.f;
  __shared__ float sBC[32];
  size_t tbase = (size_t)n * Lseq;
  for (int l=0;l<Lseq;l++){
    size_t t = tbase + l;
    if (d < 32) sBC[d] = xdbl[t*40 + 8 + d];
    __syncthreads();
    float dtv = dt[t*256 + d];
    float uv  = u [t*256 + d];
    float du  = dtv * uv;
    float acc = 0.f;
    #pragma unroll
    for (int s=0;s<16;s++){
      float dA = __expf(dtv * A[s]);
      h[s] = fmaf(h[s], dA, du * sBC[s]);
      acc  = fmaf(h[s], sBC[16+s], acc);
    }
    float zv = xz[t*512 + 256 + d];
    gy[t*256 + d] = (acc + uv*Dd) * siluf(zv);
    __syncthreads();
  }
}

// -------------------- node mean over L --------------------
__global__ void mean_kernel(const float* __restrict__ x, float* __restrict__ mean){
  int bc = blockIdx.x;      // b*32+c
  int d  = threadIdx.x;     // 128
  int b = bc >> 5, c = bc & 31;
  float s = 0.f;
  for (int l=0;l<256;l++)
    s += x[(((size_t)(b*256+l)*32+c)*128) + d];
  mean[(size_t)bc*128 + d] = s * (1.f/256.f);
}

// -------------------- Pdiag[b,c] = sigmoid(||mean[b,c] @ gw + gb||^2 / 8) --------------------
// einsum('bcc,blcd->blcd', P, x) takes the DIAGONAL of P — only P[b,c,c] matters.
__global__ void pdiag_kernel(const float* __restrict__ mean, const float* __restrict__ gw,
                             const float* __restrict__ gb, float* __restrict__ Pd){
  int bc = blockIdx.x;      // 128 blocks (b*32+c)
  int e  = threadIdx.x;     // 64 threads, one per node dim
  __shared__ float sm[128];
  sm[e]    = mean[(size_t)bc*128 + e];
  sm[e+64] = mean[(size_t)bc*128 + e + 64];
  __syncthreads();
  float acc = gb[e];
  #pragma unroll 8
  for (int dd=0; dd<128; dd++) acc = fmaf(sm[dd], gw[dd*64 + e], acc);
  float sq = acc * acc;
  // warp+block reduce over 64 threads (2 warps)
  #pragma unroll
  for (int off=16; off>0; off>>=1) sq += __shfl_down_sync(0xffffffffu, sq, off);
  __shared__ float part[2];
  if ((e & 31) == 0) part[e >> 5] = sq;
  __syncthreads();
  if (e == 0) {
    float ss = part[0] + part[1];
    Pd[bc] = 1.f / (1.f + __expf(-ss * 0.125f));
  }
}

// -------------------- xg[b,l,c,d] = Pdiag[b,c] * x[b,l,c,d] --------------------
__global__ void xg_scale_kernel(const float* __restrict__ x, const float* __restrict__ Pd,
                                float* __restrict__ xg){
  int idx = blockIdx.x*blockDim.x + threadIdx.x;   // over TOK*128/4 float4s
  int t = idx >> 5;          // (b*256+l)*32 + c  (32 float4s per (t,c) row)
  int c = t & 31;
  int b = t >> 13;           // t / 8192
  float p = Pd[b*32 + c];
  float4 v = reinterpret_cast<const float4*>(x)[idx];
  v.x *= p; v.y *= p; v.z *= p; v.w *= p;
  reinterpret_cast<float4*>(xg)[idx] = v;
}

// -------------------- launch --------------------
extern "C" void kernel_launch(void* const* d_in, const int* in_sizes, int n_in,
                              void* d_out, int out_size)
{
  const float* x        = (const float*)d_in[0];
  const float* t_w_in   = (const float*)d_in[1];
  const float* t_conv_w = (const float*)d_in[2];
  const float* t_conv_b = (const float*)d_in[3];
  const float* t_w_xproj= (const float*)d_in[4];
  const float* t_w_dt   = (const float*)d_in[5];
  const float* t_b_dt   = (const float*)d_in[6];
  const float* t_a_log  = (const float*)d_in[7];
  const float* t_d      = (const float*)d_in[8];
  const float* t_w_out  = (const float*)d_in[9];
  const float* c_w_in   = (const float*)d_in[10];
  const float* c_conv_w = (const float*)d_in[11];
  const float* c_conv_b = (const float*)d_in[12];
  const float* c_w_xproj= (const float*)d_in[13];
  const float* c_w_dt   = (const float*)d_in[14];
  const float* c_b_dt   = (const float*)d_in[15];
  const float* c_a_log  = (const float*)d_in[16];
  const float* c_d      = (const float*)d_in[17];
  const float* c_w_out  = (const float*)d_in[18];
  const float* gw_node  = (const float*)d_in[19];
  const float* gb_node  = (const float*)d_in[20];
  float* out = (float*)d_out;

  float *xt, *xz, *u, *xdbl, *dtb, *gy, *meanp, *Pd;
  cudaGetSymbolAddress((void**)&xt,   g_xt);
  cudaGetSymbolAddress((void**)&xz,   g_xz);
  cudaGetSymbolAddress((void**)&u,    g_u);
  cudaGetSymbolAddress((void**)&xdbl, g_xdbl);
  cudaGetSymbolAddress((void**)&dtb,  g_dtb);
  cudaGetSymbolAddress((void**)&gy,   g_gy);
  cudaGetSymbolAddress((void**)&meanp,g_mean);
  cudaGetSymbolAddress((void**)&Pd,   g_Pd);

  // ---------- Temporal mamba ----------
  gather_xt_kernel<<<(TOK*128)/256, 256>>>(x, xt);
  gemm_kernel<<<dim3(8,512), 256>>>(xt, t_w_in, xz, TOK, 512, 128, 0);
  conv_silu_kernel<<<128, 256>>>(xz, t_conv_w, t_conv_b, u, 256);
  gemm_kernel<<<dim3(1,512), 256>>>(u, t_w_xproj, xdbl, TOK, 40, 256, 0);
  dt_kernel<<<TOK/16, 256>>>(xdbl, t_w_dt, t_b_dt, dtb);
  scan_gate_kernel<<<128, 256>>>(dtb, u, xdbl, t_a_log, t_d, xz, gy, 256);
  gemm_kernel<<<dim3(2,512), 256>>>(gy, t_w_out, out, TOK, 128, 256, 1);

  // ---------- Channel mixing (diagonal node attention) ----------
  mean_kernel<<<128, 128>>>(x, meanp);
  pdiag_kernel<<<128, 64>>>(meanp, gw_node, gb_node, Pd);
  xg_scale_kernel<<<(TOK*128/4)/256, 256>>>(x, Pd, xt);  // xt := x_c (B*L, C, D)

  // ---------- Channel mamba ----------
  gemm_kernel<<<dim3(8,512), 256>>>(xt, c_w_in, xz, TOK, 512, 128, 0);
  conv_silu_kernel<<<1024, 256>>>(xz, c_conv_w, c_conv_b, u, 32);
  gemm_kernel<<<dim3(1,512), 256>>>(u, c_w_xproj, xdbl, TOK, 40, 256, 0);
  dt_kernel<<<TOK/16, 256>>>(xdbl, c_w_dt, c_b_dt, dtb);
  scan_gate_kernel<<<1024, 256>>>(dtb, u, xdbl, c_a_log, c_d, xz, gy, 32);
  gemm_kernel<<<dim3(2,512), 256>>>(gy, c_w_out, out + (size_t)TOK*128, TOK, 128, 256, 0);
}

// round 3
// speedup vs baseline: 1.6374x; 1.6374x over previous
#include <cuda_runtime.h>
#include <math.h>

#define TOK 32768

// -------------------- scratch (device globals; no allocs) --------------------
__device__ float g_xz  [(size_t)TOK*512];
__device__ float g_u   [(size_t)TOK*256];
__device__ float g_xdbl[(size_t)TOK*40];
__device__ float g_gy  [(size_t)TOK*256];
__device__ float g_mean[4*32*128];
__device__ float g_Pd  [4*32];

__device__ __forceinline__ float siluf(float v){ return v / (1.f + __expf(-v)); }

// ==================== big GEMM: 128x128 tile, 8x8/thread ====================
// C[M,N] = A[M,K] @ W[K,N]
// ASRC: 0 = plain row-major A
//       1 = gather from x (B,L,C,D): row r=(b*32+c)*256+l -> x[((b*256+l)*32+c)*128 + k]
//       2 = A = x (native (B*L,C,D) rows) scaled by Pd[b*32+c], c=r&31, b=r>>13
// CDST: 0 = plain row-major write
//       1 = T-scatter: row r -> out[((b*256+l)*32+c)*128 + col], r=(b*32+c)*256+l
template<int ASRC, int CDST>
__global__ void __launch_bounds__(256, 2)
gemm128_kernel(const float* __restrict__ A, const float* __restrict__ W,
               float* __restrict__ Cout, const float* __restrict__ Pd,
               int M, int N, int K)
{
  const int BK = 16;
  __shared__ float As[BK][128];
  __shared__ float Ws[BK][128];

  int tid  = threadIdx.x;
  int row0 = blockIdx.y * 128;
  int col0 = blockIdx.x * 128;

  // ---- A load mapping: thread loads row (tid>>1), 8 floats at k=(tid&1)*8
  int am = tid >> 1;
  int akq = (tid & 1) * 8;
  int ar = row0 + am;
  const float* arow;
  float ascale = 1.f;
  if (ASRC == 0) {
    arow = A + (size_t)ar * K;
  } else if (ASRC == 1) {
    int l = ar & 255; int n = ar >> 8; int c = n & 31; int b = n >> 5;
    arow = A + ((size_t)(b*8192 + l*32 + c)) * 128;
  } else {
    arow = A + (size_t)ar * 128;
    ascale = Pd[((ar >> 13) << 5) | (ar & 31)];
  }

  // ---- W load mapping: thread loads row (tid>>4), 8 floats at n=(tid&15)*8
  int wk = tid >> 4;
  int wn = (tid & 15) * 8;

  // ---- compute mapping
  int ty8 = tid >> 4;        // 0..15
  int tx  = tid & 15;        // 0..15
  int m0 = ty8 * 4;          // + 64 for second group
  int n0 = tx * 4;

  float acc[8][8];
  #pragma unroll
  for (int i=0;i<8;i++)
    #pragma unroll
    for (int j=0;j<8;j++) acc[i][j]=0.f;

  for (int k0=0; k0<K; k0+=BK) {
    float4 a0 = *reinterpret_cast<const float4*>(arow + k0 + akq);
    float4 a1 = *reinterpret_cast<const float4*>(arow + k0 + akq + 4);
    if (ASRC == 2) {
      a0.x*=ascale; a0.y*=ascale; a0.z*=ascale; a0.w*=ascale;
      a1.x*=ascale; a1.y*=ascale; a1.z*=ascale; a1.w*=ascale;
    }
    float4 w0 = *reinterpret_cast<const float4*>(W + (size_t)(k0+wk)*N + col0 + wn);
    float4 w1 = *reinterpret_cast<const float4*>(W + (size_t)(k0+wk)*N + col0 + wn + 4);
    __syncthreads();
    As[akq+0][am]=a0.x; As[akq+1][am]=a0.y; As[akq+2][am]=a0.z; As[akq+3][am]=a0.w;
    As[akq+4][am]=a1.x; As[akq+5][am]=a1.y; As[akq+6][am]=a1.z; As[akq+7][am]=a1.w;
    *reinterpret_cast<float4*>(&Ws[wk][wn])   = w0;
    *reinterpret_cast<float4*>(&Ws[wk][wn+4]) = w1;
    __syncthreads();
    #pragma unroll
    for (int k=0;k<BK;k++){
      float4 av0 = *reinterpret_cast<const float4*>(&As[k][m0]);
      float4 av1 = *reinterpret_cast<const float4*>(&As[k][m0+64]);
      float4 wv0 = *reinterpret_cast<const float4*>(&Ws[k][n0]);
      float4 wv1 = *reinterpret_cast<const float4*>(&Ws[k][n0+64]);
      float aa[8] = {av0.x,av0.y,av0.z,av0.w, av1.x,av1.y,av1.z,av1.w};
      float ww[8] = {wv0.x,wv0.y,wv0.z,wv0.w, wv1.x,wv1.y,wv1.z,wv1.w};
      #pragma unroll
      for (int i=0;i<8;i++)
        #pragma unroll
        for (int j=0;j<8;j++)
          acc[i][j] = fmaf(aa[i], ww[j], acc[i][j]);
    }
  }

  // ---- writeback
  #pragma unroll
  for (int gi=0; gi<2; gi++) {
    #pragma unroll
    for (int i=0;i<4;i++){
      int r = row0 + m0 + gi*64 + i;
      float* orow;
      if (CDST == 0) {
        orow = Cout + (size_t)r*N;
      } else {
        int l = r & 255; int n = r >> 8; int c = n & 31; int b = n >> 5;
        orow = Cout + ((size_t)(b*8192 + l*32 + c)) * 128;
      }
      float4 v0 = make_float4(acc[gi*4+i][0],acc[gi*4+i][1],acc[gi*4+i][2],acc[gi*4+i][3]);
      float4 v1 = make_float4(acc[gi*4+i][4],acc[gi*4+i][5],acc[gi*4+i][6],acc[gi*4+i][7]);
      *reinterpret_cast<float4*>(orow + col0 + n0)      = v0;
      *reinterpret_cast<float4*>(orow + col0 + n0 + 64) = v1;
    }
  }
}

// ==================== small-N GEMM (xproj, N=40): 64x64 tile ====================
__global__ void gemm_kernel(const float* __restrict__ A, const float* __restrict__ W,
                            float* __restrict__ Cout, int M, int N, int K)
{
  const int BM=64, BN=64, BK=16;
  __shared__ float As[BK][BM];
  __shared__ float Ws[BK][BN];
  int tid = threadIdx.x;
  int tr = tid >> 4;
  int tc = tid & 15;
  int row0 = blockIdx.y * BM;
  int col0 = blockIdx.x * BN;

  float acc[4][4];
  #pragma unroll
  for (int i=0;i<4;i++)
    #pragma unroll
    for (int j=0;j<4;j++) acc[i][j]=0.f;

  int ar = tid >> 2;
  int ak = (tid & 3) * 4;
  int wr = tid >> 4;
  int wc = (tid & 15) * 4;

  for (int k0=0; k0<K; k0+=BK){
    float4 av = *reinterpret_cast<const float4*>(A + (size_t)(row0+ar)*K + k0 + ak);
    As[ak+0][ar]=av.x; As[ak+1][ar]=av.y; As[ak+2][ar]=av.z; As[ak+3][ar]=av.w;
    int wcol = col0 + wc;
    #pragma unroll
    for (int j=0;j<4;j++)
      Ws[wr][wc+j] = (wcol+j < N) ? W[(size_t)(k0+wr)*N + wcol + j] : 0.f;
    __syncthreads();
    #pragma unroll
    for (int k=0;k<BK;k++){
      float4 a = *reinterpret_cast<const float4*>(&As[k][tr*4]);
      float4 w = *reinterpret_cast<const float4*>(&Ws[k][tc*4]);
      acc[0][0]=fmaf(a.x,w.x,acc[0][0]); acc[0][1]=fmaf(a.x,w.y,acc[0][1]);
      acc[0][2]=fmaf(a.x,w.z,acc[0][2]); acc[0][3]=fmaf(a.x,w.w,acc[0][3]);
      acc[1][0]=fmaf(a.y,w.x,acc[1][0]); acc[1][1]=fmaf(a.y,w.y,acc[1][1]);
      acc[1][2]=fmaf(a.y,w.z,acc[1][2]); acc[1][3]=fmaf(a.y,w.w,acc[1][3]);
      acc[2][0]=fmaf(a.z,w.x,acc[2][0]); acc[2][1]=fmaf(a.z,w.y,acc[2][1]);
      acc[2][2]=fmaf(a.z,w.z,acc[2][2]); acc[2][3]=fmaf(a.z,w.w,acc[2][3]);
      acc[3][0]=fmaf(a.w,w.x,acc[3][0]); acc[3][1]=fmaf(a.w,w.y,acc[3][1]);
      acc[3][2]=fmaf(a.w,w.z,acc[3][2]); acc[3][3]=fmaf(a.w,w.w,acc[3][3]);
    }
    __syncthreads();
  }

  int row = row0 + tr*4;
  int col = col0 + tc*4;
  #pragma unroll
  for (int i=0;i<4;i++){
    int r = row+i;
    #pragma unroll
    for (int j=0;j<4;j++)
      if (col+j < N) Cout[(size_t)r*N + col + j] = acc[i][j];
  }
}

// ==================== causal depthwise conv (DC=4) + bias + silu ====================
__global__ void conv_silu_kernel(const float* __restrict__ xz, const float* __restrict__ cw,
                                 const float* __restrict__ cb, float* __restrict__ uo, int Lseq){
  int n = blockIdx.x; int d = threadIdx.x;
  float w0=cw[d], w1=cw[256+d], w2=cw[512+d], w3=cw[768+d];
  float b = cb[d];
  const float* base = xz + (size_t)n*Lseq*512;
  float* ub = uo + (size_t)n*Lseq*256;
  float x0=0.f, x1=0.f, x2=0.f;
  for (int l=0;l<Lseq;l+=4){
    float xa = base[(size_t)(l+0)*512 + d];
    float xb = base[(size_t)(l+1)*512 + d];
    float xc = base[(size_t)(l+2)*512 + d];
    float xd = base[(size_t)(l+3)*512 + d];
    float va = fmaf(x0,w0, fmaf(x1,w1, fmaf(x2,w2, fmaf(xa,w3, b))));
    float vb = fmaf(x1,w0, fmaf(x2,w1, fmaf(xa,w2, fmaf(xb,w3, b))));
    float vc = fmaf(x2,w0, fmaf(xa,w1, fmaf(xb,w2, fmaf(xc,w3, b))));
    float vd = fmaf(xa,w0, fmaf(xb,w1, fmaf(xc,w2, fmaf(xd,w3, b))));
    ub[(size_t)(l+0)*256 + d] = siluf(va);
    ub[(size_t)(l+1)*256 + d] = siluf(vb);
    ub[(size_t)(l+2)*256 + d] = siluf(vc);
    ub[(size_t)(l+3)*256 + d] = siluf(vd);
    x0=xb; x1=xc; x2=xd;
  }
}

// ==================== fused dt + selective scan + output gating ====================
// reads xdbl (dt-in cols 0..7, B cols 8..23, C cols 24..39), computes
// dt = softplus(xdbl[:,:8]@w_dt + b_dt) inline, scans, gates with silu(z).
template<int LSEQ>
__global__ void scan_fused_kernel(const float* __restrict__ xdbl,
                                  const float* __restrict__ w_dt, const float* __restrict__ b_dt,
                                  const float* __restrict__ u, const float* __restrict__ a_log,
                                  const float* __restrict__ dskip, const float* __restrict__ xz,
                                  float* __restrict__ gy)
{
  __shared__ float sx[LSEQ*40];
  int n = blockIdx.x; int d = threadIdx.x;     // 256 threads
  size_t tbase = (size_t)n * LSEQ;

  // whole-sequence xdbl chunk is contiguous: perfect coalesced preload
  for (int i=d; i<LSEQ*40; i+=256) sx[i] = xdbl[tbase*40 + i];

  float w[8];
  #pragma unroll
  for (int r=0;r<8;r++) w[r] = w_dt[r*256 + d];
  float bdt = b_dt[d];
  float A[16];
  bool geo = true;
  #pragma unroll
  for (int s=0;s<16;s++){
    A[s] = -__expf(a_log[d*16+s]);
    geo = geo && (fabsf(A[s] + (float)(s+1)) < 1e-4f*(float)(s+1));
  }
  float Dd = dskip[d];
  float h[16];
  #pragma unroll
  for (int s=0;s<16;s++) h[s]=0.f;
  __syncthreads();

  float uv = u[tbase*256 + d];
  float zv = xz[tbase*512 + 256 + d];

  if (geo) {
    // A[s] == -(s+1): dA[s] = e1^(s+1), e1 = exp(-dt). Power-tree, no per-s MUFU.
    for (int l=0; l<LSEQ; l++){
      size_t t = tbase + l;
      float u_nxt=0.f, z_nxt=0.f;
      if (l+1 < LSEQ) { u_nxt = u[(t+1)*256+d]; z_nxt = xz[(t+1)*512+256+d]; }
      const float* row = &sx[l*40];
      float a0 = fmaf(row[0],w[0], fmaf(row[1],w[1], fmaf(row[2],w[2], fmaf(row[3],w[3], bdt))));
      float a1 = fmaf(row[4],w[4], fmaf(row[5],w[5], fmaf(row[6],w[6], fmaf(row[7],w[7], 0.f))));
      float adt = a0 + a1;
      float dtv = (adt > 20.f) ? adt : log1pf(__expf(adt));
      float du = dtv * uv;
      float e1 = __expf(-dtv);
      float e2 = e1*e1, e4 = e2*e2, e8 = e4*e4;
      float p[16];
      p[0]=e1;    p[1]=e2;    p[2]=e2*e1;  p[3]=e4;
      p[4]=e4*e1; p[5]=e4*e2; p[6]=e4*p[2];p[7]=e8;
      p[8]=e8*e1; p[9]=e8*e2; p[10]=e8*p[2]; p[11]=e8*e4;
      p[12]=e8*p[4]; p[13]=e8*p[5]; p[14]=e8*p[6]; p[15]=e8*e8;
      float ac0=0.f, ac1=0.f, ac2=0.f, ac3=0.f;
      #pragma unroll
      for (int s=0;s<16;s+=4){
        h[s+0] = fmaf(h[s+0], p[s+0], du*row[8+s+0]);
        h[s+1] = fmaf(h[s+1], p[s+1], du*row[8+s+1]);
        h[s+2] = fmaf(h[s+2], p[s+2], du*row[8+s+2]);
        h[s+3] = fmaf(h[s+3], p[s+3], du*row[8+s+3]);
        ac0 = fmaf(h[s+0], row[24+s+0], ac0);
        ac1 = fmaf(h[s+1], row[24+s+1], ac1);
        ac2 = fmaf(h[s+2], row[24+s+2], ac2);
        ac3 = fmaf(h[s+3], row[24+s+3], ac3);
      }
      float acc = (ac0+ac1)+(ac2+ac3);
      gy[t*256+d] = (acc + uv*Dd) * siluf(zv);
      uv = u_nxt; zv = z_nxt;
    }
  } else {
    // generic path
    for (int l=0; l<LSEQ; l++){
      size_t t = tbase + l;
      float u_nxt=0.f, z_nxt=0.f;
      if (l+1 < LSEQ) { u_nxt = u[(t+1)*256+d]; z_nxt = xz[(t+1)*512+256+d]; }
      const float* row = &sx[l*40];
      float adt = bdt;
      #pragma unroll
      for (int r=0;r<8;r++) adt = fmaf(row[r], w[r], adt);
      float dtv = (adt > 20.f) ? adt : log1pf(__expf(adt));
      float du = dtv * uv;
      float acc = 0.f;
      #pragma unroll
      for (int s=0;s<16;s++){
        float dA = __expf(dtv * A[s]);
        h[s] = fmaf(h[s], dA, du*row[8+s]);
        acc  = fmaf(h[s], row[24+s], acc);
      }
      gy[t*256+d] = (acc + uv*Dd) * siluf(zv);
      uv = u_nxt; zv = z_nxt;
    }
  }
}

// ==================== node mean over L ====================
__global__ void mean_kernel(const float* __restrict__ x, float* __restrict__ mean){
  int bc = blockIdx.x;
  int d  = threadIdx.x;
  int b = bc >> 5, c = bc & 31;
  const float* base = x + ((size_t)b*8192 + c)*128 + d;
  float s0=0.f, s1=0.f, s2=0.f, s3=0.f;
  #pragma unroll 4
  for (int l=0;l<256;l+=4){
    s0 += base[(size_t)(l+0)*4096];
    s1 += base[(size_t)(l+1)*4096];
    s2 += base[(size_t)(l+2)*4096];
    s3 += base[(size_t)(l+3)*4096];
  }
  mean[(size_t)bc*128 + d] = (s0+s1+s2+s3) * (1.f/256.f);
}

// ==================== Pdiag[b,c] = sigmoid(||mean@gw+gb||^2/8) ====================
__global__ void pdiag_kernel(const float* __restrict__ mean, const float* __restrict__ gw,
                             const float* __restrict__ gb, float* __restrict__ Pd){
  int bc = blockIdx.x;
  int e  = threadIdx.x;     // 64
  __shared__ float sm[128];
  sm[e]    = mean[(size_t)bc*128 + e];
  sm[e+64] = mean[(size_t)bc*128 + e + 64];
  __syncthreads();
  float acc = gb[e];
  #pragma unroll 8
  for (int dd=0; dd<128; dd++) acc = fmaf(sm[dd], gw[dd*64 + e], acc);
  float sq = acc * acc;
  #pragma unroll
  for (int off=16; off>0; off>>=1) sq += __shfl_down_sync(0xffffffffu, sq, off);
  __shared__ float part[2];
  if ((e & 31) == 0) part[e >> 5] = sq;
  __syncthreads();
  if (e == 0) {
    float ss = part[0] + part[1];
    Pd[bc] = 1.f / (1.f + __expf(-ss * 0.125f));
  }
}

// ==================== launch ====================
extern "C" void kernel_launch(void* const* d_in, const int* in_sizes, int n_in,
                              void* d_out, int out_size)
{
  const float* x        = (const float*)d_in[0];
  const float* t_w_in   = (const float*)d_in[1];
  const float* t_conv_w = (const float*)d_in[2];
  const float* t_conv_b = (const float*)d_in[3];
  const float* t_w_xproj= (const float*)d_in[4];
  const float* t_w_dt   = (const float*)d_in[5];
  const float* t_b_dt   = (const float*)d_in[6];
  const float* t_a_log  = (const float*)d_in[7];
  const float* t_d      = (const float*)d_in[8];
  const float* t_w_out  = (const float*)d_in[9];
  const float* c_w_in   = (const float*)d_in[10];
  const float* c_conv_w = (const float*)d_in[11];
  const float* c_conv_b = (const float*)d_in[12];
  const float* c_w_xproj= (const float*)d_in[13];
  const float* c_w_dt   = (const float*)d_in[14];
  const float* c_b_dt   = (const float*)d_in[15];
  const float* c_a_log  = (const float*)d_in[16];
  const float* c_d      = (const float*)d_in[17];
  const float* c_w_out  = (const float*)d_in[18];
  const float* gw_node  = (const float*)d_in[19];
  const float* gb_node  = (const float*)d_in[20];
  float* out = (float*)d_out;

  float *xz, *u, *xdbl, *gy, *meanp, *Pd;
  cudaGetSymbolAddress((void**)&xz,   g_xz);
  cudaGetSymbolAddress((void**)&u,    g_u);
  cudaGetSymbolAddress((void**)&xdbl, g_xdbl);
  cudaGetSymbolAddress((void**)&gy,   g_gy);
  cudaGetSymbolAddress((void**)&meanp,g_mean);
  cudaGetSymbolAddress((void**)&Pd,   g_Pd);

  // ---------- Temporal mamba ----------
  gemm128_kernel<1,0><<<dim3(4,256), 256>>>(x, t_w_in, xz, nullptr, TOK, 512, 128);
  conv_silu_kernel<<<128, 256>>>(xz, t_conv_w, t_conv_b, u, 256);
  gemm_kernel<<<dim3(1,512), 256>>>(u, t_w_xproj, xdbl, TOK, 40, 256);
  scan_fused_kernel<256><<<128, 256>>>(xdbl, t_w_dt, t_b_dt, u, t_a_log, t_d, xz, gy);
  gemm128_kernel<0,1><<<dim3(1,256), 256>>>(gy, t_w_out, out, nullptr, TOK, 128, 256);

  // ---------- Channel mixing (diagonal node attention) ----------
  mean_kernel<<<128, 128>>>(x, meanp);
  pdiag_kernel<<<128, 64>>>(meanp, gw_node, gb_node, Pd);

  // ---------- Channel mamba (Pd-scale fused into w_in GEMM) ----------
  gemm128_kernel<2,0><<<dim3(4,256), 256>>>(x, c_w_in, xz, Pd, TOK, 512, 128);
  conv_silu_kernel<<<1024, 256>>>(xz, c_conv_w, c_conv_b, u, 32);
  gemm_kernel<<<dim3(1,512), 256>>>(u, c_w_xproj, xdbl, TOK, 40, 256);
  scan_fused_kernel<32><<<1024, 256>>>(xdbl, c_w_dt, c_b_dt, u, c_a_log, c_d, xz, gy);
  gemm128_kernel<0,0><<<dim3(1,256), 256>>>(gy, c_w_out, out + (size_t)TOK*128, nullptr, TOK, 128, 256);
}

// round 4
// speedup vs baseline: 2.1269x; 1.2989x over previous
#include <cuda_runtime.h>
#include <math.h>
#include <stdint.h>

#define TOK 32768

// -------------------- scratch (device globals; no allocs) --------------------
__device__ float g_xz  [(size_t)TOK*512];
__device__ float g_u   [(size_t)TOK*256];
__device__ float g_xdbl[(size_t)TOK*40];
__device__ float g_gy  [(size_t)TOK*256];
__device__ float g_mean[4*32*128];
__device__ float g_Pd  [4*32];

__device__ __forceinline__ float siluf(float v){ return v / (1.f + __expf(-v)); }

__device__ __forceinline__ uint32_t f2tf32(float v){
  uint32_t r; asm("cvt.rna.tf32.f32 %0, %1;" : "=r"(r) : "f"(v)); return r;
}
__device__ __forceinline__ void mma_tf32(float* d,
    uint32_t a0,uint32_t a1,uint32_t a2,uint32_t a3,uint32_t b0,uint32_t b1){
  asm volatile("mma.sync.aligned.m16n8k8.row.col.f32.tf32.tf32.f32 "
    "{%0,%1,%2,%3}, {%4,%5,%6,%7}, {%8,%9}, {%0,%1,%2,%3};"
    : "+f"(d[0]),"+f"(d[1]),"+f"(d[2]),"+f"(d[3])
    : "r"(a0),"r"(a1),"r"(a2),"r"(a3),"r"(b0),"r"(b1));
}

// ==================== tf32 tensor-core GEMM: 128x128 tile ====================
// C[M,N] = A[M,K] @ W[K,N]; N % 128 == 0, K % 16 == 0, M % 128 == 0.
// ASRC: 0 plain A; 1 gather from x (B,L,C,D) by T-permuted row; 2 x scaled by Pd
// CDST: 0 plain write; 1 T-scatter (N==128 tile col == d)
template<int ASRC, int CDST>
__global__ void __launch_bounds__(256)
gemm_tf32_kernel(const float* __restrict__ A, const float* __restrict__ W,
                 float* __restrict__ Cout, const float* __restrict__ Pd,
                 int M, int N, int K)
{
  const int RS = 136;                       // smem row stride (floats)
  __shared__ uint32_t As[2][16*RS];
  __shared__ uint32_t Ws[2][16*RS];

  int tid  = threadIdx.x;
  int row0 = blockIdx.y * 128;
  int col0 = blockIdx.x * 128;
  int lane = tid & 31, warp = tid >> 5;
  int wm = (warp & 1) * 64;                 // warp M offset (2 warps in M)
  int wn = (warp >> 1) * 32;                // warp N offset (4 warps in N)
  int g  = lane >> 2, tig = lane & 3;

  // ---- global A mapping: row = tid>>1, 8 floats at k=(tid&1)*8
  int am  = tid >> 1;
  int akq = (tid & 1) * 8;
  int ar  = row0 + am;
  const float* arow;
  float ascale = 1.f;
  if (ASRC == 0) {
    arow = A + (size_t)ar * K;
  } else if (ASRC == 1) {
    int l = ar & 255; int n = ar >> 8; int c = n & 31; int b = n >> 5;
    arow = A + ((size_t)(b*8192 + l*32 + c)) * 128;
  } else {
    arow = A + (size_t)ar * 128;
    ascale = Pd[((ar >> 13) << 5) | (ar & 31)];
  }
  // ---- global W mapping: k-row = tid>>4, 8 floats at n=(tid&15)*8
  int wk  = tid >> 4;
  int wn8 = (tid & 15) * 8;

  float acc[4][4][4];
  #pragma unroll
  for (int i=0;i<4;i++)
    #pragma unroll
    for (int j=0;j<4;j++)
      #pragma unroll
      for (int q=0;q<4;q++) acc[i][j][q]=0.f;

  float ast[8], wst[8];
  // prologue: load tile 0
  {
    float4 a0 = *reinterpret_cast<const float4*>(arow + akq);
    float4 a1 = *reinterpret_cast<const float4*>(arow + akq + 4);
    ast[0]=a0.x; ast[1]=a0.y; ast[2]=a0.z; ast[3]=a0.w;
    ast[4]=a1.x; ast[5]=a1.y; ast[6]=a1.z; ast[7]=a1.w;
    float4 w0 = *reinterpret_cast<const float4*>(W + (size_t)wk*N + col0 + wn8);
    float4 w1 = *reinterpret_cast<const float4*>(W + (size_t)wk*N + col0 + wn8 + 4);
    wst[0]=w0.x; wst[1]=w0.y; wst[2]=w0.z; wst[3]=w0.w;
    wst[4]=w1.x; wst[5]=w1.y; wst[6]=w1.z; wst[7]=w1.w;
  }
  {
    #pragma unroll
    for (int q=0;q<8;q++) As[0][(akq+q)*RS + am] = f2tf32(ast[q]*ascale);
    #pragma unroll
    for (int q=0;q<8;q++) Ws[0][wk*RS + wn8 + q] = f2tf32(wst[q]);
  }
  __syncthreads();

  int nt = K >> 4;
  for (int t=0; t<nt; t++) {
    int cur = t & 1;
    if (t+1 < nt) {
      int k0 = (t+1) << 4;
      float4 a0 = *reinterpret_cast<const float4*>(arow + k0 + akq);
      float4 a1 = *reinterpret_cast<const float4*>(arow + k0 + akq + 4);
      ast[0]=a0.x; ast[1]=a0.y; ast[2]=a0.z; ast[3]=a0.w;
      ast[4]=a1.x; ast[5]=a1.y; ast[6]=a1.z; ast[7]=a1.w;
      float4 w0 = *reinterpret_cast<const float4*>(W + (size_t)(k0+wk)*N + col0 + wn8);
      float4 w1 = *reinterpret_cast<const float4*>(W + (size_t)(k0+wk)*N + col0 + wn8 + 4);
      wst[0]=w0.x; wst[1]=w0.y; wst[2]=w0.z; wst[3]=w0.w;
      wst[4]=w1.x; wst[5]=w1.y; wst[6]=w1.z; wst[7]=w1.w;
    }
    #pragma unroll
    for (int ks=0; ks<16; ks+=8) {
      uint32_t af[4][4], bf[4][2];
      #pragma unroll
      for (int i=0;i<4;i++){
        int mr = wm + i*16 + g;
        af[i][0] = As[cur][(ks+tig  )*RS + mr];
        af[i][1] = As[cur][(ks+tig  )*RS + mr + 8];
        af[i][2] = As[cur][(ks+tig+4)*RS + mr];
        af[i][3] = As[cur][(ks+tig+4)*RS + mr + 8];
      }
      #pragma unroll
      for (int j=0;j<4;j++){
        int nc = wn + j*8 + g;
        bf[j][0] = Ws[cur][(ks+tig  )*RS + nc];
        bf[j][1] = Ws[cur][(ks+tig+4)*RS + nc];
      }
      #pragma unroll
      for (int i=0;i<4;i++)
        #pragma unroll
        for (int j=0;j<4;j++)
          mma_tf32(acc[i][j], af[i][0],af[i][1],af[i][2],af[i][3], bf[j][0],bf[j][1]);
    }
    if (t+1 < nt) {
      int nxt = (t+1) & 1;
      #pragma unroll
      for (int q=0;q<8;q++) As[nxt][(akq+q)*RS + am] = f2tf32(ast[q]*ascale);
      #pragma unroll
      for (int q=0;q<8;q++) Ws[nxt][wk*RS + wn8 + q] = f2tf32(wst[q]);
      __syncthreads();
    }
  }

  // ---- epilogue
  #pragma unroll
  for (int i=0;i<4;i++){
    int r_lo = row0 + wm + i*16 + g;
    #pragma unroll
    for (int half=0; half<2; half++){
      int r = r_lo + half*8;
      float* orow;
      if (CDST == 0) {
        orow = Cout + (size_t)r * N;
      } else {
        int l = r & 255; int n = r >> 8; int c = n & 31; int b = n >> 5;
        orow = Cout + ((size_t)(b*8192 + l*32 + c)) * 128;
      }
      #pragma unroll
      for (int j=0;j<4;j++){
        int cc = col0 + wn + j*8 + tig*2;
        float2 v = make_float2(acc[i][j][half*2], acc[i][j][half*2+1]);
        *reinterpret_cast<float2*>(orow + cc) = v;
      }
    }
  }
}

// ==================== small-N fp32 GEMM (xproj, N=40): 64x64 tile ====================
__global__ void gemm_kernel(const float* __restrict__ A, const float* __restrict__ W,
                            float* __restrict__ Cout, int M, int N, int K)
{
  const int BM=64, BN=64, BK=16;
  __shared__ float As[BK][BM];
  __shared__ float Ws[BK][BN];
  int tid = threadIdx.x;
  int tr = tid >> 4;
  int tc = tid & 15;
  int row0 = blockIdx.y * BM;
  int col0 = blockIdx.x * BN;

  float acc[4][4];
  #pragma unroll
  for (int i=0;i<4;i++)
    #pragma unroll
    for (int j=0;j<4;j++) acc[i][j]=0.f;

  int ar = tid >> 2;
  int ak = (tid & 3) * 4;
  int wr = tid >> 4;
  int wc = (tid & 15) * 4;

  for (int k0=0; k0<K; k0+=BK){
    float4 av = *reinterpret_cast<const float4*>(A + (size_t)(row0+ar)*K + k0 + ak);
    As[ak+0][ar]=av.x; As[ak+1][ar]=av.y; As[ak+2][ar]=av.z; As[ak+3][ar]=av.w;
    int wcol = col0 + wc;
    #pragma unroll
    for (int j=0;j<4;j++)
      Ws[wr][wc+j] = (wcol+j < N) ? W[(size_t)(k0+wr)*N + wcol + j] : 0.f;
    __syncthreads();
    #pragma unroll
    for (int k=0;k<BK;k++){
      float4 a = *reinterpret_cast<const float4*>(&As[k][tr*4]);
      float4 w = *reinterpret_cast<const float4*>(&Ws[k][tc*4]);
      acc[0][0]=fmaf(a.x,w.x,acc[0][0]); acc[0][1]=fmaf(a.x,w.y,acc[0][1]);
      acc[0][2]=fmaf(a.x,w.z,acc[0][2]); acc[0][3]=fmaf(a.x,w.w,acc[0][3]);
      acc[1][0]=fmaf(a.y,w.x,acc[1][0]); acc[1][1]=fmaf(a.y,w.y,acc[1][1]);
      acc[1][2]=fmaf(a.y,w.z,acc[1][2]); acc[1][3]=fmaf(a.y,w.w,acc[1][3]);
      acc[2][0]=fmaf(a.z,w.x,acc[2][0]); acc[2][1]=fmaf(a.z,w.y,acc[2][1]);
      acc[2][2]=fmaf(a.z,w.z,acc[2][2]); acc[2][3]=fmaf(a.z,w.w,acc[2][3]);
      acc[3][0]=fmaf(a.w,w.x,acc[3][0]); acc[3][1]=fmaf(a.w,w.y,acc[3][1]);
      acc[3][2]=fmaf(a.w,w.z,acc[3][2]); acc[3][3]=fmaf(a.w,w.w,acc[3][3]);
    }
    __syncthreads();
  }

  int row = row0 + tr*4;
  int col = col0 + tc*4;
  #pragma unroll
  for (int i=0;i<4;i++){
    int r = row+i;
    #pragma unroll
    for (int j=0;j<4;j++)
      if (col+j < N) Cout[(size_t)r*N + col + j] = acc[i][j];
  }
}

// ==================== causal depthwise conv (DC=4) + bias + silu ====================
__global__ void conv_silu_kernel(const float* __restrict__ xz, const float* __restrict__ cw,
                                 const float* __restrict__ cb, float* __restrict__ uo, int Lseq){
  int n = blockIdx.x; int d = threadIdx.x;
  float w0=cw[d], w1=cw[256+d], w2=cw[512+d], w3=cw[768+d];
  float b = cb[d];
  const float* base = xz + (size_t)n*Lseq*512;
  float* ub = uo + (size_t)n*Lseq*256;
  float x0=0.f, x1=0.f, x2=0.f;
  for (int l=0;l<Lseq;l+=4){
    float xa = base[(size_t)(l+0)*512 + d];
    float xb = base[(size_t)(l+1)*512 + d];
    float xc = base[(size_t)(l+2)*512 + d];
    float xd = base[(size_t)(l+3)*512 + d];
    float va = fmaf(x0,w0, fmaf(x1,w1, fmaf(x2,w2, fmaf(xa,w3, b))));
    float vb = fmaf(x1,w0, fmaf(x2,w1, fmaf(xa,w2, fmaf(xb,w3, b))));
    float vc = fmaf(x2,w0, fmaf(xa,w1, fmaf(xb,w2, fmaf(xc,w3, b))));
    float vd = fmaf(xa,w0, fmaf(xb,w1, fmaf(xc,w2, fmaf(xd,w3, b))));
    ub[(size_t)(l+0)*256 + d] = siluf(va);
    ub[(size_t)(l+1)*256 + d] = siluf(vb);
    ub[(size_t)(l+2)*256 + d] = siluf(vc);
    ub[(size_t)(l+3)*256 + d] = siluf(vd);
    x0=xb; x1=xc; x2=xd;
  }
}

// ==================== fused dt + selective scan + output gating ====================
template<int LSEQ>
__global__ void scan_fused_kernel(const float* __restrict__ xdbl,
                                  const float* __restrict__ w_dt, const float* __restrict__ b_dt,
                                  const float* __restrict__ u, const float* __restrict__ a_log,
                                  const float* __restrict__ dskip, const float* __restrict__ xz,
                                  float* __restrict__ gy)
{
  __shared__ float sx[LSEQ*40];
  int n = blockIdx.x; int d = threadIdx.x;     // 256 threads
  size_t tbase = (size_t)n * LSEQ;

  for (int i=d; i<LSEQ*40; i+=256) sx[i] = xdbl[tbase*40 + i];

  float w[8];
  #pragma unroll
  for (int r=0;r<8;r++) w[r] = w_dt[r*256 + d];
  float bdt = b_dt[d];
  float A[16];
  bool geo = true;
  #pragma unroll
  for (int s=0;s<16;s++){
    A[s] = -__expf(a_log[d*16+s]);
    geo = geo && (fabsf(A[s] + (float)(s+1)) < 1e-4f*(float)(s+1));
  }
  float Dd = dskip[d];
  float h[16];
  #pragma unroll
  for (int s=0;s<16;s++) h[s]=0.f;
  __syncthreads();

  float uv = u[tbase*256 + d];
  float zv = xz[tbase*512 + 256 + d];

  if (geo) {
    for (int l=0; l<LSEQ; l++){
      size_t t = tbase + l;
      float u_nxt=0.f, z_nxt=0.f;
      if (l+1 < LSEQ) { u_nxt = u[(t+1)*256+d]; z_nxt = xz[(t+1)*512+256+d]; }
      const float* row = &sx[l*40];
      float a0 = fmaf(row[0],w[0], fmaf(row[1],w[1], fmaf(row[2],w[2], fmaf(row[3],w[3], bdt))));
      float a1 = fmaf(row[4],w[4], fmaf(row[5],w[5], fmaf(row[6],w[6], fmaf(row[7],w[7], 0.f))));
      float adt = a0 + a1;
      float dtv = (adt > 20.f) ? adt : log1pf(__expf(adt));
      float du = dtv * uv;
      float e1 = __expf(-dtv);
      float e2 = e1*e1, e4 = e2*e2, e8 = e4*e4;
      float p[16];
      p[0]=e1;    p[1]=e2;    p[2]=e2*e1;  p[3]=e4;
      p[4]=e4*e1; p[5]=e4*e2; p[6]=e4*p[2];p[7]=e8;
      p[8]=e8*e1; p[9]=e8*e2; p[10]=e8*p[2]; p[11]=e8*e4;
      p[12]=e8*p[4]; p[13]=e8*p[5]; p[14]=e8*p[6]; p[15]=e8*e8;
      float ac0=0.f, ac1=0.f, ac2=0.f, ac3=0.f;
      #pragma unroll
      for (int s=0;s<16;s+=4){
        h[s+0] = fmaf(h[s+0], p[s+0], du*row[8+s+0]);
        h[s+1] = fmaf(h[s+1], p[s+1], du*row[8+s+1]);
        h[s+2] = fmaf(h[s+2], p[s+2], du*row[8+s+2]);
        h[s+3] = fmaf(h[s+3], p[s+3], du*row[8+s+3]);
        ac0 = fmaf(h[s+0], row[24+s+0], ac0);
        ac1 = fmaf(h[s+1], row[24+s+1], ac1);
        ac2 = fmaf(h[s+2], row[24+s+2], ac2);
        ac3 = fmaf(h[s+3], row[24+s+3], ac3);
      }
      float acc = (ac0+ac1)+(ac2+ac3);
      gy[t*256+d] = (acc + uv*Dd) * siluf(zv);
      uv = u_nxt; zv = z_nxt;
    }
  } else {
    for (int l=0; l<LSEQ; l++){
      size_t t = tbase + l;
      float u_nxt=0.f, z_nxt=0.f;
      if (l+1 < LSEQ) { u_nxt = u[(t+1)*256+d]; z_nxt = xz[(t+1)*512+256+d]; }
      const float* row = &sx[l*40];
      float adt = bdt;
      #pragma unroll
      for (int r=0;r<8;r++) adt = fmaf(row[r], w[r], adt);
      float dtv = (adt > 20.f) ? adt : log1pf(__expf(adt));
      float du = dtv * uv;
      float acc = 0.f;
      #pragma unroll
      for (int s=0;s<16;s++){
        float dA = __expf(dtv * A[s]);
        h[s] = fmaf(h[s], dA, du*row[8+s]);
        acc  = fmaf(h[s], row[24+s], acc);
      }
      gy[t*256+d] = (acc + uv*Dd) * siluf(zv);
      uv = u_nxt; zv = z_nxt;
    }
  }
}

// ==================== node mean over L ====================
__global__ void mean_kernel(const float* __restrict__ x, float* __restrict__ mean){
  int bc = blockIdx.x;
  int d  = threadIdx.x;
  int b = bc >> 5, c = bc & 31;
  const float* base = x + ((size_t)b*8192 + c)*128 + d;
  float s0=0.f, s1=0.f, s2=0.f, s3=0.f;
  #pragma unroll 4
  for (int l=0;l<256;l+=4){
    s0 += base[(size_t)(l+0)*4096];
    s1 += base[(size_t)(l+1)*4096];
    s2 += base[(size_t)(l+2)*4096];
    s3 += base[(size_t)(l+3)*4096];
  }
  mean[(size_t)bc*128 + d] = (s0+s1+s2+s3) * (1.f/256.f);
}

// ==================== Pdiag[b,c] = sigmoid(||mean@gw+gb||^2/8) ====================
__global__ void pdiag_kernel(const float* __restrict__ mean, const float* __restrict__ gw,
                             const float* __restrict__ gb, float* __restrict__ Pd){
  int bc = blockIdx.x;
  int e  = threadIdx.x;     // 64
  __shared__ float sm[128];
  sm[e]    = mean[(size_t)bc*128 + e];
  sm[e+64] = mean[(size_t)bc*128 + e + 64];
  __syncthreads();
  float acc = gb[e];
  #pragma unroll 8
  for (int dd=0; dd<128; dd++) acc = fmaf(sm[dd], gw[dd*64 + e], acc);
  float sq = acc * acc;
  #pragma unroll
  for (int off=16; off>0; off>>=1) sq += __shfl_down_sync(0xffffffffu, sq, off);
  __shared__ float part[2];
  if ((e & 31) == 0) part[e >> 5] = sq;
  __syncthreads();
  if (e == 0) {
    float ss = part[0] + part[1];
    Pd[bc] = 1.f / (1.f + __expf(-ss * 0.125f));
  }
}

// ==================== launch ====================
extern "C" void kernel_launch(void* const* d_in, const int* in_sizes, int n_in,
                              void* d_out, int out_size)
{
  const float* x        = (const float*)d_in[0];
  const float* t_w_in   = (const float*)d_in[1];
  const float* t_conv_w = (const float*)d_in[2];
  const float* t_conv_b = (const float*)d_in[3];
  const float* t_w_xproj= (const float*)d_in[4];
  const float* t_w_dt   = (const float*)d_in[5];
  const float* t_b_dt   = (const float*)d_in[6];
  const float* t_a_log  = (const float*)d_in[7];
  const float* t_d      = (const float*)d_in[8];
  const float* t_w_out  = (const float*)d_in[9];
  const float* c_w_in   = (const float*)d_in[10];
  const float* c_conv_w = (const float*)d_in[11];
  const float* c_conv_b = (const float*)d_in[12];
  const float* c_w_xproj= (const float*)d_in[13];
  const float* c_w_dt   = (const float*)d_in[14];
  const float* c_b_dt   = (const float*)d_in[15];
  const float* c_a_log  = (const float*)d_in[16];
  const float* c_d      = (const float*)d_in[17];
  const float* c_w_out  = (const float*)d_in[18];
  const float* gw_node  = (const float*)d_in[19];
  const float* gb_node  = (const float*)d_in[20];
  float* out = (float*)d_out;

  float *xz, *u, *xdbl, *gy, *meanp, *Pd;
  cudaGetSymbolAddress((void**)&xz,   g_xz);
  cudaGetSymbolAddress((void**)&u,    g_u);
  cudaGetSymbolAddress((void**)&xdbl, g_xdbl);
  cudaGetSymbolAddress((void**)&gy,   g_gy);
  cudaGetSymbolAddress((void**)&meanp,g_mean);
  cudaGetSymbolAddress((void**)&Pd,   g_Pd);

  // ---------- Temporal mamba ----------
  gemm_tf32_kernel<1,0><<<dim3(4,256), 256>>>(x, t_w_in, xz, nullptr, TOK, 512, 128);
  conv_silu_kernel<<<128, 256>>>(xz, t_conv_w, t_conv_b, u, 256);
  gemm_kernel<<<dim3(1,512), 256>>>(u, t_w_xproj, xdbl, TOK, 40, 256);
  scan_fused_kernel<256><<<128, 256>>>(xdbl, t_w_dt, t_b_dt, u, t_a_log, t_d, xz, gy);
  gemm_tf32_kernel<0,1><<<dim3(1,256), 256>>>(gy, t_w_out, out, nullptr, TOK, 128, 256);

  // ---------- Channel mixing (diagonal node attention) ----------
  mean_kernel<<<128, 128>>>(x, meanp);
  pdiag_kernel<<<128, 64>>>(meanp, gw_node, gb_node, Pd);

  // ---------- Channel mamba (Pd-scale fused into w_in GEMM) ----------
  gemm_tf32_kernel<2,0><<<dim3(4,256), 256>>>(x, c_w_in, xz, Pd, TOK, 512, 128);
  conv_silu_kernel<<<1024, 256>>>(xz, c_conv_w, c_conv_b, u, 32);
  gemm_kernel<<<dim3(1,512), 256>>>(u, c_w_xproj, xdbl, TOK, 40, 256);
  scan_fused_kernel<32><<<1024, 256>>>(xdbl, c_w_dt, c_b_dt, u, c_a_log, c_d, xz, gy);
  gemm_tf32_kernel<0,0><<<dim3(1,256), 256>>>(gy, c_w_out, out + (size_t)TOK*128, nullptr, TOK, 128, 256);
}